// round 1
// baseline (speedup 1.0000x reference)
#include <cuda_runtime.h>
#include <stdint.h>

#define IMH 1024
#define IMW 1024
#define NB  8
#define WPR 32   // 32-bit words per image row (1024/32)

// Bit-packed strong/weak planes: 1 MB each. Static device scratch (no allocs).
__device__ uint32_t g_strong[NB * IMH * WPR];
__device__ uint32_t g_weak[NB * IMH * WPR];

// ---------------------------------------------------------------------------
// K1: fused gaussian blur + sobel + magnitude + NMS + double threshold.
// 32x32 output tile per block, 256 threads (32x8). Bit-packs results via ballot.
// ---------------------------------------------------------------------------
__global__ void __launch_bounds__(256) canny_front(const float* __restrict__ in)
{
    __shared__ float   s_in [38][40];
    __shared__ float   s_bl [36][40];
    __shared__ float   s_mag[34][40];
    __shared__ uint8_t s_bin[34][36];

    const int tx = threadIdx.x, ty = threadIdx.y;
    const int bx = blockIdx.x, by = blockIdx.y, b = blockIdx.z;
    const int x0 = bx * 32, y0 = by * 32;
    const float* img = in + (size_t)b * IMH * IMW;

    // --- load input with halo 3 (zeros outside image) ---
    for (int r = ty; r < 38; r += 8) {
        int gy = y0 + r - 3;
        for (int c = tx; c < 38; c += 32) {
            int gx = x0 + c - 3;
            float v = 0.0f;
            if ((unsigned)gy < IMH && (unsigned)gx < IMW) v = img[gy * IMW + gx];
            s_in[r][c] = v;
        }
    }
    __syncthreads();

    // --- gaussian blur (zero outside image: conv output padding is zeros) ---
    for (int r = ty; r < 36; r += 8) {
        int gy = y0 + r - 2;
        for (int c = tx; c < 36; c += 32) {
            int gx = x0 + c - 2;
            float v = 0.0f;
            if ((unsigned)gy < IMH && (unsigned)gx < IMW) {
                v = 0.0625f * s_in[r  ][c] + 0.125f * s_in[r  ][c+1] + 0.0625f * s_in[r  ][c+2]
                  + 0.125f  * s_in[r+1][c] + 0.25f  * s_in[r+1][c+1] + 0.125f  * s_in[r+1][c+2]
                  + 0.0625f * s_in[r+2][c] + 0.125f * s_in[r+2][c+1] + 0.0625f * s_in[r+2][c+2];
            }
            s_bl[r][c] = v;
        }
    }
    __syncthreads();

    // --- sobel magnitude + quantized direction bin ---
    for (int r = ty; r < 34; r += 8) {
        int gy = y0 + r - 1;
        for (int c = tx; c < 34; c += 32) {
            int gxp = x0 + c - 1;
            float m = 0.0f;
            int bin = 0;
            if ((unsigned)gy < IMH && (unsigned)gxp < IMW) {
                float b00 = s_bl[r  ][c], b01 = s_bl[r  ][c+1], b02 = s_bl[r  ][c+2];
                float b10 = s_bl[r+1][c],                        b12 = s_bl[r+1][c+2];
                float b20 = s_bl[r+2][c], b21 = s_bl[r+2][c+1], b22 = s_bl[r+2][c+2];
                float gx = (b02 - b00) + 2.0f * (b12 - b10) + (b22 - b20);
                float gv = (b20 - b00) + 2.0f * (b21 - b01) + (b22 - b02);
                m = sqrtf(gx * gx + gv * gv);
                float ax = fabsf(gx), ay = fabsf(gv);
                bool same_sign = ((__float_as_uint(gx) ^ __float_as_uint(gv)) >> 31) == 0u;
                if (ay < 0.41421356237309503f * ax)       bin = 0;   // horizontal
                else if (ay >= 2.414213562373095f * ax)   bin = 2;   // vertical
                else                                      bin = same_sign ? 1 : 3;
            }
            s_mag[r][c] = m;
            if (c < 36) s_bin[r][c] = (uint8_t)bin;
        }
    }
    __syncthreads();

    // --- NMS + double threshold, ballot-pack into bit planes ---
    #pragma unroll
    for (int k = 0; k < 4; k++) {
        int r = ty + 8 * k;          // 0..31
        int c = tx;                  // 0..31
        float m  = s_mag[r + 1][c + 1];
        int  bin = s_bin[r + 1][c + 1];
        // neighbor offsets:
        //  bin0: (0,+1)/(0,-1)  bin1: (-1,+1)/(+1,-1)  bin2: (-1,0)/(+1,0)  bin3: (-1,-1)/(+1,+1)
        int dc = (bin <= 1) ? 1 : ((bin == 2) ? 0 : -1);
        int r1 = (bin == 0) ? (r + 1) : r;
        int r2 = (bin == 0) ? (r + 1) : (r + 2);
        float n1 = s_mag[r1][c + 1 + dc];
        float n2 = s_mag[r2][c + 1 - dc];
        float sup = (m >= n1 && m >= n2) ? m : 0.0f;
        bool strong = (sup >= 0.3f);
        bool weak   = (sup >= 0.1f) && (sup < 0.3f);
        uint32_t sb = __ballot_sync(0xffffffffu, strong);
        uint32_t wb = __ballot_sync(0xffffffffu, weak);
        if (tx == 0) {
            int gy = y0 + r;
            int idx = (b * IMH + gy) * WPR + bx;
            g_strong[idx] = sb;
            g_weak[idx]   = wb;
        }
    }
}

// ---------------------------------------------------------------------------
// K2: 16 hysteresis dilation iterations entirely in SMEM on bit-packed masks,
// then expand to float output. Tile: full 1024-px width x 64 rows interior,
// 16-row vertical halo each side (96 data rows + 2 zero guard rows).
// Guard/stale-halo error front advances 1 row per iteration; interior starts
// 16 rows in, so 16 iterations are exact.
// ---------------------------------------------------------------------------
__global__ void __launch_bounds__(256) canny_hyst(float* __restrict__ out)
{
    __shared__ uint32_t E [98][34];   // col 0 and 33 are zero guards; rows 0,97 guards
    __shared__ uint32_t Wk[98][34];

    const int tid = threadIdx.x;
    const int by  = blockIdx.x;       // 0..15 (row tiles of 64)
    const int b   = blockIdx.y;       // image
    const int r0  = by * 64;

    // --- load bit planes with halo; zeros outside ---
    for (int i = tid; i < 98 * 34; i += 256) {
        int m = i / 34, c = i % 34;
        uint32_t e = 0, w = 0;
        int gr = r0 - 16 + (m - 1);
        int wc = c - 1;
        if (m >= 1 && m <= 96 && (unsigned)wc < WPR && (unsigned)gr < IMH) {
            int idx = (b * IMH + gr) * WPR + wc;
            e = g_strong[idx];
            w = g_weak[idx];
        }
        (&E[0][0])[i]  = e;
        (&Wk[0][0])[i] = w;
    }
    __syncthreads();

    const int col   = tid & 31;       // data word col 0..31 -> smem col+1
    const int g     = tid >> 5;       // row-strip id 0..7
    const int rbase = g * 12;         // data rows rbase..rbase+11 -> smem rows +1

    uint32_t w[12];
    #pragma unroll
    for (int k = 0; k < 12; k++) w[k] = Wk[rbase + 1 + k][col + 1];

    for (int it = 0; it < 16; it++) {
        uint32_t ne[12];
        // horizontal dilation h(row) = m | m<<1 | m>>1 | L>>31 | R<<31
        uint32_t mm, l, rr;
        mm = E[rbase][col + 1]; l = E[rbase][col]; rr = E[rbase][col + 2];
        uint32_t hp = mm | (mm << 1) | (mm >> 1) | (l >> 31) | (rr << 31);
        mm = E[rbase + 1][col + 1]; l = E[rbase + 1][col]; rr = E[rbase + 1][col + 2];
        uint32_t ecur = mm;
        uint32_t hc = mm | (mm << 1) | (mm >> 1) | (l >> 31) | (rr << 31);
        #pragma unroll
        for (int k = 0; k < 12; k++) {
            mm = E[rbase + 2 + k][col + 1];
            l  = E[rbase + 2 + k][col];
            rr = E[rbase + 2 + k][col + 2];
            uint32_t hn = mm | (mm << 1) | (mm >> 1) | (l >> 31) | (rr << 31);
            ne[k] = ecur | (w[k] & (hp | hc | hn));
            hp = hc; hc = hn; ecur = mm;
        }
        __syncthreads();
        #pragma unroll
        for (int k = 0; k < 12; k++) E[rbase + 1 + k][col + 1] = ne[k];
        __syncthreads();
    }

    // --- expand interior (data rows 16..79 == smem rows 17..80) to float ---
    float* outImg = out + (size_t)b * IMH * IMW + (size_t)r0 * IMW;
    for (int i = tid; i < 64 * 1024; i += 256) {
        int rr2 = i >> 10;
        int x   = i & 1023;
        uint32_t word = E[17 + rr2][(x >> 5) + 1];
        outImg[i] = (float)((word >> (x & 31)) & 1u);
    }
}

extern "C" void kernel_launch(void* const* d_in, const int* in_sizes, int n_in,
                              void* d_out, int out_size)
{
    const float* in = (const float*)d_in[0];
    float* out = (float*)d_out;

    dim3 blk1(32, 8);
    dim3 grd1(32, 32, NB);
    canny_front<<<grd1, blk1>>>(in);

    dim3 grd2(16, NB);
    canny_hyst<<<grd2, 256>>>(out);
}

// round 4
// speedup vs baseline: 1.3612x; 1.3612x over previous
#include <cuda_runtime.h>
#include <stdint.h>

#define IMH 1024
#define IMW 1024
#define NB  8
#define WPR 32   // 32-bit words per image row

// Bit-packed strong/weak planes (static device scratch, no allocs)
__device__ uint32_t g_strong[NB * IMH * WPR];
__device__ uint32_t g_weak[NB * IMH * WPR];

#define ROWS1 32   // output rows per canny_front block

// ---------------------------------------------------------------------------
// K1: rolling pipeline over full 1024-wide rows, 512 threads x 2 cols each.
// Math is bit-identical to the round-1 passing kernel: direct 9-tap gaussian,
// direct sobel on blurred field, same expression ordering.
// Row rings (depth 4) in smem carry raw, blurred, and magnitude rows.
// Pipeline at iter r: store raw(r), bl(r-2), mag(r-4); sync;
// compute bl(r-1), mag+bin(r-3), NMS+threshold+pack row(r-5).
// Ring depth 4 with one sync/iter: an overwritten slot's last reader is 2
// iterations behind, separated by a sync.
// ---------------------------------------------------------------------------
__global__ void __launch_bounds__(512) canny_front(const float* __restrict__ in)
{
    __shared__ float s_raw[4][1026];
    __shared__ float s_bl [4][1026];
    __shared__ float s_mag[4][1026];

    const int tid = threadIdx.x;              // 0..511
    const int b   = blockIdx.y;
    const int y0  = blockIdx.x * ROWS1;
    const float* img = in + (size_t)b * IMH * IMW;
    const int cx = tid * 2;                   // columns cx, cx+1

    // zero guard columns (index 0 and 1025)
    if (tid < 8) {
        int s = tid & 3, g = (tid >> 2) * 1025;
        s_raw[s][g] = 0.f; s_bl[s][g] = 0.f; s_mag[s][g] = 0.f;
    }

    float blpx = 0.f, blpy = 0.f;    // bl(r-2) pending store
    float magpx = 0.f, magpy = 0.f;  // mag(r-4) pending store
    int bin_m1x = 0, bin_m1y = 0, bin_m2x = 0, bin_m2y = 0;

    const int r_start = y0 - 3, r_end = y0 + ROWS1 + 4;

    float2 rv = make_float2(0.f, 0.f);
    if ((unsigned)r_start < IMH)
        rv = ((const float2*)(img + (size_t)r_start * IMW))[tid];

    for (int r = r_start; r <= r_end; ++r) {
        // ---- store phase ----
        {
            float* pr = s_raw[r & 3];
            float* pb = s_bl[(r - 2) & 3];
            float* pm = s_mag[(r - 4) & 3];
            pr[1 + cx] = rv.x;  pr[2 + cx] = rv.y;
            pb[1 + cx] = blpx;  pb[2 + cx] = blpy;
            pm[1 + cx] = magpx; pm[2 + cx] = magpy;
        }
        __syncthreads();

        // prefetch raw(r+1)
        float2 rvn = make_float2(0.f, 0.f);
        if ((unsigned)(r + 1) < IMH)
            rvn = ((const float2*)(img + (size_t)(r + 1) * IMW))[tid];

        // ---- blur(r-1): direct 9-tap, round-1 expression ----
        float blnx = 0.f, blny = 0.f;
        if (r >= y0 - 1 && (unsigned)(r - 1) < IMH) {
            const float* t = s_raw[(r - 2) & 3];
            const float* m = s_raw[(r - 1) & 3];
            const float* d = s_raw[r & 3];
            float t0 = t[cx], t1 = t[cx+1], t2 = t[cx+2], t3 = t[cx+3];
            float m0 = m[cx], m1 = m[cx+1], m2 = m[cx+2], m3 = m[cx+3];
            float d0 = d[cx], d1 = d[cx+1], d2 = d[cx+2], d3 = d[cx+3];
            blnx = 0.0625f * t0 + 0.125f * t1 + 0.0625f * t2
                 + 0.125f  * m0 + 0.25f  * m1 + 0.125f  * m2
                 + 0.0625f * d0 + 0.125f * d1 + 0.0625f * d2;
            blny = 0.0625f * t1 + 0.125f * t2 + 0.0625f * t3
                 + 0.125f  * m1 + 0.25f  * m2 + 0.125f  * m3
                 + 0.0625f * d1 + 0.125f * d2 + 0.0625f * d3;
        }

        // ---- sobel + mag + bin at row r-3: round-1 expressions ----
        float magnx = 0.f, magny = 0.f; int binnx = 0, binny = 0;
        if (r >= y0 + 2 && (unsigned)(r - 3) < IMH) {
            const float* u = s_bl[(r - 4) & 3];
            const float* c = s_bl[(r - 3) & 3];
            const float* d = s_bl[(r - 2) & 3];
            float u0 = u[cx], u1 = u[cx+1], u2 = u[cx+2], u3 = u[cx+3];
            float c0 = c[cx], c1 = c[cx+1], c2 = c[cx+2], c3 = c[cx+3];
            float d0 = d[cx], d1 = d[cx+1], d2 = d[cx+2], d3 = d[cx+3];
            {
                float gx = (u2 - u0) + 2.0f * (c2 - c0) + (d2 - d0);
                float gy = (d0 - u0) + 2.0f * (d1 - u1) + (d2 - u2);
                magnx = sqrtf(gx * gx + gy * gy);
                float ax = fabsf(gx), ay = fabsf(gy);
                bool ss = ((__float_as_uint(gx) ^ __float_as_uint(gy)) >> 31) == 0u;
                binnx = (ay < 0.41421356237309503f * ax) ? 0 :
                        (ay >= 2.414213562373095f  * ax) ? 2 : (ss ? 1 : 3);
            }
            {
                float gx = (u3 - u1) + 2.0f * (c3 - c1) + (d3 - d1);
                float gy = (d1 - u1) + 2.0f * (d2 - u2) + (d3 - u3);
                magny = sqrtf(gx * gx + gy * gy);
                float ax = fabsf(gx), ay = fabsf(gy);
                bool ss = ((__float_as_uint(gx) ^ __float_as_uint(gy)) >> 31) == 0u;
                binny = (ay < 0.41421356237309503f * ax) ? 0 :
                        (ay >= 2.414213562373095f  * ax) ? 2 : (ss ? 1 : 3);
            }
        }

        // ---- NMS + double threshold + bitpack at row r-5 ----
        if (r >= y0 + 5) {
            const float* mU = s_mag[(r - 6) & 3];
            const float* mC = s_mag[(r - 5) & 3];
            const float* mD = s_mag[(r - 4) & 3];
            bool s0, w0, s1, w1;
            {
                float m = mC[1 + cx];
                int bin = bin_m2x;
                int dc = (bin <= 1) ? 1 : ((bin == 2) ? 0 : -1);
                const float* p1 = (bin == 0) ? mC : mU;
                const float* p2 = (bin == 0) ? mC : mD;
                float n1 = p1[1 + cx + dc], n2 = p2[1 + cx - dc];
                float sup = (m >= n1 && m >= n2) ? m : 0.f;
                s0 = sup >= 0.3f;
                w0 = (sup >= 0.1f) && (sup < 0.3f);
            }
            {
                float m = mC[2 + cx];
                int bin = bin_m2y;
                int dc = (bin <= 1) ? 1 : ((bin == 2) ? 0 : -1);
                const float* p1 = (bin == 0) ? mC : mU;
                const float* p2 = (bin == 0) ? mC : mD;
                float n1 = p1[2 + cx + dc], n2 = p2[2 + cx - dc];
                float sup = (m >= n1 && m >= n2) ? m : 0.f;
                s1 = sup >= 0.3f;
                w1 = (sup >= 0.1f) && (sup < 0.3f);
            }
            unsigned vs = (s0 ? 1u : 0u) | (s1 ? 2u : 0u);
            unsigned vw = (w0 ? 1u : 0u) | (w1 ? 2u : 0u);
            unsigned mask = ((tid >> 4) & 1) ? 0xFFFF0000u : 0x0000FFFFu;
            int sh = 2 * (tid & 15);
            unsigned ws = __reduce_or_sync(mask, vs << sh);
            unsigned ww = __reduce_or_sync(mask, vw << sh);
            if ((tid & 15) == 0) {
                int idx = (b * IMH + (r - 5)) * WPR + (cx >> 5);
                g_strong[idx] = ws;
                g_weak[idx]   = ww;
            }
        }

        // ---- ring shifts ----
        blpx = blnx; blpy = blny;
        magpx = magnx; magpy = magny;
        bin_m2x = bin_m1x; bin_m2y = bin_m1y; bin_m1x = binnx; bin_m1y = binny;
        rv = rvn;
    }
}

// ---------------------------------------------------------------------------
// K2: 16 hysteresis iterations on bit-packed masks, 16-row interior tiles
// (full 1024 width) with 16-row halos -> grid 64x8 = 512 blocks.
// Stale-halo front advances 1 row/iter; interior starts 16 rows in => exact.
// Epilogue expands the interior directly to the float output.
// ---------------------------------------------------------------------------
__global__ void __launch_bounds__(256) canny_hyst(float* __restrict__ out)
{
    __shared__ uint32_t E [50][34];   // rows 0,49 + cols 0,33 are zero guards
    __shared__ uint32_t Wk[50][34];

    const int tid = threadIdx.x;
    const int by  = blockIdx.x;       // 0..63
    const int b   = blockIdx.y;
    const int r0  = by * 16;

    for (int i = tid; i < 50 * 34; i += 256) {
        int m = i / 34, c = i % 34;
        uint32_t e = 0, w = 0;
        int gr = r0 - 16 + (m - 1);
        int wc = c - 1;
        if (m >= 1 && m <= 48 && (unsigned)wc < WPR && (unsigned)gr < IMH) {
            int idx = (b * IMH + gr) * WPR + wc;
            e = g_strong[idx];
            w = g_weak[idx];
        }
        (&E[0][0])[i]  = e;
        (&Wk[0][0])[i] = w;
    }
    __syncthreads();

    const int col   = tid & 31;
    const int wrp   = tid >> 5;
    const int rbase = wrp * 6;        // 6 data rows per warp (8*6 = 48)

    uint32_t w6[6];
    #pragma unroll
    for (int k = 0; k < 6; k++) w6[k] = Wk[rbase + 1 + k][col + 1];

    for (int it = 0; it < 16; ++it) {
        uint32_t ne[6];
        uint32_t mm, l, rr;
        mm = E[rbase][col + 1]; l = E[rbase][col]; rr = E[rbase][col + 2];
        uint32_t hp = mm | (mm << 1) | (mm >> 1) | (l >> 31) | (rr << 31);
        mm = E[rbase + 1][col + 1]; l = E[rbase + 1][col]; rr = E[rbase + 1][col + 2];
        uint32_t ec = mm;
        uint32_t hc = mm | (mm << 1) | (mm >> 1) | (l >> 31) | (rr << 31);
        #pragma unroll
        for (int k = 0; k < 6; k++) {
            mm = E[rbase + 2 + k][col + 1];
            l  = E[rbase + 2 + k][col];
            rr = E[rbase + 2 + k][col + 2];
            uint32_t hn = mm | (mm << 1) | (mm >> 1) | (l >> 31) | (rr << 31);
            ne[k] = ec | (w6[k] & (hp | hc | hn));
            hp = hc; hc = hn; ec = mm;
        }
        __syncthreads();
        #pragma unroll
        for (int k = 0; k < 6; k++) E[rbase + 1 + k][col + 1] = ne[k];
        __syncthreads();
    }

    // expand interior (data rows 16..31 == smem rows 17..32) to float output
    float4* o = (float4*)(out + (size_t)b * IMH * IMW + (size_t)r0 * IMW);
    for (int u = tid; u < 16 * 256; u += 256) {
        int row = u >> 8;             // 256 float4 per image row
        int q   = u & 255;
        int colpx = q << 2;
        uint32_t word = E[17 + row][(colpx >> 5) + 1];
        int sh = colpx & 31;
        float4 v;
        v.x = (float)((word >> sh)       & 1u);
        v.y = (float)((word >> (sh + 1)) & 1u);
        v.z = (float)((word >> (sh + 2)) & 1u);
        v.w = (float)((word >> (sh + 3)) & 1u);
        o[(row << 8) + q] = v;
    }
}

extern "C" void kernel_launch(void* const* d_in, const int* in_sizes, int n_in,
                              void* d_out, int out_size)
{
    const float* in = (const float*)d_in[0];
    float* out = (float*)d_out;

    dim3 g1(IMH / ROWS1, NB);     // 32 x 8
    canny_front<<<g1, 512>>>(in);

    dim3 g2(64, NB);              // 64 x 8
    canny_hyst<<<g2, 256>>>(out);
}